// round 4
// baseline (speedup 1.0000x reference)
#include <cuda_runtime.h>
#include <cuda_bf16.h>

#define BDIM 512
#define S_LEN 4096
#define B_ROWS 4096
#define NBLK 304          // 152 SMs * 2 resident blocks

__device__ float g_partial[NBLK];
__device__ unsigned int g_count = 0;

__device__ __forceinline__ float ex2_approx(float x) {
    float r; asm("ex2.approx.f32 %0, %1;" : "=f"(r) : "f"(x)); return r;
}
__device__ __forceinline__ float lg2_approx(float x) {
    float r; asm("lg2.approx.f32 %0, %1;" : "=f"(r) : "f"(x)); return r;
}

__global__ __launch_bounds__(BDIM, 2) void mtcut_persistent_kernel(
    const float* __restrict__ cut_y,
    const int*   __restrict__ cut_label,
    const float* __restrict__ rerank_y,
    float* __restrict__ out)
{
    const int t    = threadIdx.x;
    const int lane = t & 31;
    const int wid  = t >> 5;

    __shared__ int   wsum[16];
    __shared__ int   woff[17];
    __shared__ float se[16], sl[16];
    __shared__ unsigned int s_rank;

    float block_acc = 0.f;    // only meaningful in thread 0

    // ---- prefetch first row ----
    int b = blockIdx.x;
    float4 pya, pyb; int4 pla, plb;
    {
        const float4* y4 = reinterpret_cast<const float4*>(cut_y + (size_t)b * S_LEN);
        const int4*   l4 = reinterpret_cast<const int4*>(cut_label + (size_t)b * S_LEN);
        pya = __ldcs(&y4[2 * t]);
        pyb = __ldcs(&y4[2 * t + 1]);
        pla = __ldcs(&l4[2 * t]);
        plb = __ldcs(&l4[2 * t + 1]);
    }

    for (; b < B_ROWS; b += NBLK) {
        // consume prefetched row
        float4 ya = pya, yb = pyb;
        int4   la = pla, lb = plb;

        // issue next row's loads NOW — in flight during scan barriers below
        int bn = b + NBLK;
        if (bn < B_ROWS) {
            const float4* y4 = reinterpret_cast<const float4*>(cut_y + (size_t)bn * S_LEN);
            const int4*   l4 = reinterpret_cast<const int4*>(cut_label + (size_t)bn * S_LEN);
            pya = __ldcs(&y4[2 * t]);
            pyb = __ldcs(&y4[2 * t + 1]);
            pla = __ldcs(&l4[2 * t]);
            plb = __ldcs(&l4[2 * t + 1]);
        }

        int   lab[8] = {la.x, la.y, la.z, la.w, lb.x, lb.y, lb.z, lb.w};
        float yv[8]  = {ya.x, ya.y, ya.z, ya.w, yb.x, yb.y, yb.z, yb.w};

        // independent work first: sum of lg2(y)
        float lg2sum = 0.f;
        #pragma unroll
        for (int j = 0; j < 8; j++) lg2sum += lg2_approx(yv[j]);

        // label prefix sum
        int tsum = 0;
        #pragma unroll
        for (int j = 0; j < 8; j++) tsum += lab[j];

        int incl = tsum;
        #pragma unroll
        for (int d = 1; d < 32; d <<= 1) {
            int v = __shfl_up_sync(0xffffffffu, incl, d);
            if (lane >= d) incl += v;
        }

        if (lane == 31) wsum[wid] = incl;
        __syncthreads();
        if (t == 0) {
            int acc = 0;
            #pragma unroll
            for (int w = 0; w < 16; w++) { woff[w] = acc; acc += wsum[w]; }
            woff[16] = acc;
        }
        __syncthreads();

        const float T = (float)woff[16];
        int c = woff[wid] + incl - tsum;

        // exp(r/tau) = ex2( 2c / ((k+T)*tau*ln2) )
        const float Cx = 2.0f / (0.95f * 0.69314718055994531f);
        float esum = 0.f;
        const float kbase = (float)(t * 8) + T;
        #pragma unroll
        for (int j = 0; j < 8; j++) {
            c += lab[j];
            float arg = __fdividef((float)c * Cx, kbase + (float)(j + 1));
            esum += ex2_approx(arg);
        }

        // block reduce esum, lg2sum
        #pragma unroll
        for (int d = 16; d; d >>= 1) {
            esum   += __shfl_down_sync(0xffffffffu, esum, d);
            lg2sum += __shfl_down_sync(0xffffffffu, lg2sum, d);
        }
        if (lane == 0) { se[wid] = esum; sl[wid] = lg2sum; }
        __syncthreads();
        if (t == 0) {
            float e = 0.f, l = 0.f;
            #pragma unroll
            for (int w = 0; w < 16; w++) { e += se[w]; l += sl[w]; }
            float lsum = l * 0.69314718055994531f;
            float2 pn = reinterpret_cast<const float2*>(rerank_y)[b];
            float hinge = fmaxf(0.f, pn.y - pn.x + 1.0f);
            block_acc += hinge - lsum / e;
        }
        __syncthreads();   // protect se/sl/wsum reuse next iteration
    }

    // ---- block done: publish partial, last block finalizes ----
    if (t == 0) {
        g_partial[blockIdx.x] = block_acc * (1.0f / (float)B_ROWS);
        __threadfence();                        // once per block, at the end
        s_rank = atomicAdd(&g_count, 1u);
    }
    __syncthreads();

    if (s_rank == NBLK - 1) {
        float a = (t < NBLK) ? g_partial[t] : 0.f;
        #pragma unroll
        for (int d = 16; d; d >>= 1)
            a += __shfl_down_sync(0xffffffffu, a, d);
        __shared__ float sa[16];
        if (lane == 0) sa[wid] = a;
        __syncthreads();
        if (t == 0) {
            float av = 0.f;
            #pragma unroll
            for (int w = 0; w < 16; w++) av += sa[w];
            out[0] = av;
            g_count = 0;    // reset for next graph replay
        }
    }
}

extern "C" void kernel_launch(void* const* d_in, const int* in_sizes, int n_in,
                              void* d_out, int out_size)
{
    const float* rerank_y  = (const float*)d_in[0];   // (8192,1)
    const float* cut_y     = (const float*)d_in[1];   // (4096,4096,1)
    const int*   cut_label = (const int*)d_in[3];     // (4096,4096)
    float* out = (float*)d_out;

    mtcut_persistent_kernel<<<NBLK, BDIM>>>(cut_y, cut_label, rerank_y, out);
}

// round 5
// speedup vs baseline: 1.0598x; 1.0598x over previous
#include <cuda_runtime.h>
#include <cuda_bf16.h>

#define BDIM 512
#define S_LEN 4096
#define B_ROWS 4096

__device__ float        g_accum = 0.0f;
__device__ unsigned int g_count = 0;

__device__ __forceinline__ float ex2_approx(float x) {
    float r; asm("ex2.approx.f32 %0, %1;" : "=f"(r) : "f"(x)); return r;
}
__device__ __forceinline__ float lg2_approx(float x) {
    float r; asm("lg2.approx.f32 %0, %1;" : "=f"(r) : "f"(x)); return r;
}
// opaque zero: forces a register dependency the compiler can't fold away
__device__ __forceinline__ unsigned opaque_zero(unsigned v) {
    unsigned z;
    asm volatile("and.b32 %0, %1, 0;" : "=r"(z) : "r"(v));
    return z;
}

__global__ __launch_bounds__(BDIM) void mtcut_row_kernel(
    const float* __restrict__ cut_y,
    const int*   __restrict__ cut_label,
    const float* __restrict__ rerank_y,
    float* __restrict__ out)
{
    const int b    = blockIdx.x;
    const int t    = threadIdx.x;
    const int lane = t & 31;
    const int wid  = t >> 5;

    const float4* y4 = reinterpret_cast<const float4*>(cut_y + (size_t)b * S_LEN);
    const int4*   l4 = reinterpret_cast<const int4*>(cut_label + (size_t)b * S_LEN);

    float4 ya = __ldcs(&y4[2 * t]);
    float4 yb = __ldcs(&y4[2 * t + 1]);
    int4   la = __ldcs(&l4[2 * t]);
    int4   lb = __ldcs(&l4[2 * t + 1]);

    int   lab[8] = {la.x, la.y, la.z, la.w, lb.x, lb.y, lb.z, lb.w};
    float yv[8]  = {ya.x, ya.y, ya.z, ya.w, yb.x, yb.y, yb.z, yb.w};

    // independent work first: sum of lg2(y) fills load/scan latency
    float lg2sum = 0.f;
    #pragma unroll
    for (int j = 0; j < 8; j++) lg2sum += lg2_approx(yv[j]);

    // per-thread label sum + warp inclusive scan
    int tsum = 0;
    #pragma unroll
    for (int j = 0; j < 8; j++) tsum += lab[j];

    int incl = tsum;
    #pragma unroll
    for (int d = 1; d < 32; d <<= 1) {
        int v = __shfl_up_sync(0xffffffffu, incl, d);
        if (lane >= d) incl += v;
    }

    __shared__ int wsum[16];
    if (lane == 31) wsum[wid] = incl;
    __syncthreads();

    // every thread computes its own warp offset + row total (broadcast LDS)
    int off = 0, tot = 0;
    #pragma unroll
    for (int w = 0; w < 16; w++) {
        int v = wsum[w];
        tot += v;
        if (w < wid) off += v;
    }

    const float T = (float)tot;
    int c = off + incl - tsum;            // exclusive prefix for this thread

    // exp(r/tau) = ex2( 2c / ((k+T)*tau*ln2) ); r=2c/(k+T) is the f1 weight
    const float Cx = 2.0f / (0.95f * 0.69314718055994531f);
    float esum = 0.f;
    const float kbase = (float)(t * 8) + T;
    #pragma unroll
    for (int j = 0; j < 8; j++) {
        c += lab[j];
        float arg = __fdividef((float)c * Cx, kbase + (float)(j + 1));
        esum += ex2_approx(arg);
    }

    // block reduce esum, lg2sum
    #pragma unroll
    for (int d = 16; d; d >>= 1) {
        esum   += __shfl_down_sync(0xffffffffu, esum, d);
        lg2sum += __shfl_down_sync(0xffffffffu, lg2sum, d);
    }
    __shared__ float se[16], sl[16];
    if (lane == 0) { se[wid] = esum; sl[wid] = lg2sum; }
    __syncthreads();

    if (t == 0) {
        float e = 0.f, l = 0.f;
        #pragma unroll
        for (int w = 0; w < 16; w++) { e += se[w]; l += sl[w]; }
        float lsum = l * 0.69314718055994531f;           // lg2 -> ln
        float2 pn = reinterpret_cast<const float2*>(rerank_y)[b];
        float hinge = fmaxf(0.f, pn.y - pn.x + 1.0f);
        float contrib = (hinge - lsum / e) * (1.0f / (float)B_ROWS);

        // accumulate at L2 (no fence, no L1 flush)
        float oldv = atomicAdd(&g_accum, contrib);
        // force the counter increment to depend on the accumulate's completion
        unsigned z0 = opaque_zero(__float_as_uint(oldv));
        unsigned rank = atomicAdd(&g_count, 1u + z0);

        if (rank == B_ROWS - 1) {
            // last block: dependency-ordered coherent read of the total
            unsigned z1 = opaque_zero(rank);
            float total = atomicAdd(&g_accum, __uint_as_float(z1));  // += +0.0f
            out[0] = total;
            // reset globals for the next graph replay, ordered after the read
            unsigned z2 = opaque_zero(__float_as_uint(total));
            atomicExch(&g_accum, __uint_as_float(z2));               // = 0.0f
            atomicExch(&g_count, z2);                                // = 0
        }
    }
}

extern "C" void kernel_launch(void* const* d_in, const int* in_sizes, int n_in,
                              void* d_out, int out_size)
{
    const float* rerank_y  = (const float*)d_in[0];   // (8192,1)
    const float* cut_y     = (const float*)d_in[1];   // (4096,4096,1)
    const int*   cut_label = (const int*)d_in[3];     // (4096,4096)
    float* out = (float*)d_out;

    mtcut_row_kernel<<<B_ROWS, BDIM>>>(cut_y, cut_label, rerank_y, out);
}

// round 6
// speedup vs baseline: 1.1324x; 1.0685x over previous
#include <cuda_runtime.h>
#include <cuda_bf16.h>

#define BDIM 512
#define S_LEN 4096
#define B_ROWS 4096

__device__ float        g_accum = 0.0f;
__device__ unsigned int g_count = 0;

__device__ __forceinline__ float ex2_approx(float x) {
    float r; asm("ex2.approx.f32 %0, %1;" : "=f"(r) : "f"(x)); return r;
}
__device__ __forceinline__ float lg2_approx(float x) {
    float r; asm("lg2.approx.f32 %0, %1;" : "=f"(r) : "f"(x)); return r;
}
__device__ __forceinline__ unsigned opaque_zero(unsigned v) {
    unsigned z;
    asm volatile("and.b32 %0, %1, 0;" : "=r"(z) : "r"(v));
    return z;
}

__global__ __launch_bounds__(BDIM) void mtcut_row_kernel(
    const float* __restrict__ cut_y,
    const int*   __restrict__ cut_label,
    const float* __restrict__ rerank_y,
    float* __restrict__ out)
{
    const int b    = blockIdx.x;
    const int t    = threadIdx.x;
    const int lane = t & 31;
    const int wid  = t >> 5;

    const float4* y4 = reinterpret_cast<const float4*>(cut_y + (size_t)b * S_LEN);
    const int4*   l4 = reinterpret_cast<const int4*>(cut_label + (size_t)b * S_LEN);

    float4 ya = __ldcs(&y4[2 * t]);
    float4 yb = __ldcs(&y4[2 * t + 1]);
    int4   la = __ldcs(&l4[2 * t]);
    int4   lb = __ldcs(&l4[2 * t + 1]);

    // labels -> float once (values 0/1; float math exact up to 2^24)
    float labf[8] = {(float)la.x, (float)la.y, (float)la.z, (float)la.w,
                     (float)lb.x, (float)lb.y, (float)lb.z, (float)lb.w};

    // sum(log y) = log(prod y): pairwise tree, ONE lg2 per thread.
    // y in (1e-4, 1) -> prod >= 1e-32 > FLT_MIN, no underflow.
    float p01 = ya.x * ya.y, p23 = ya.z * ya.w;
    float p45 = yb.x * yb.y, p67 = yb.z * yb.w;
    float prod = (p01 * p23) * (p45 * p67);
    float lg2sum = lg2_approx(prod);

    // per-thread label sum + warp inclusive scan (float)
    float tsum = 0.f;
    #pragma unroll
    for (int j = 0; j < 8; j++) tsum += labf[j];

    float incl = tsum;
    #pragma unroll
    for (int d = 1; d < 32; d <<= 1) {
        float v = __shfl_up_sync(0xffffffffu, incl, d);
        if (lane >= d) incl += v;
    }

    __shared__ float wsum[16];
    __shared__ float woff[16];
    __shared__ float stot;
    if (lane == 31) wsum[wid] = incl;
    __syncthreads();

    // level-2 scan in warp 0 (shuffle), broadcast via smem
    if (wid == 0) {
        float v = (lane < 16) ? wsum[lane] : 0.f;
        float s = v;
        #pragma unroll
        for (int d = 1; d < 16; d <<= 1) {
            float u = __shfl_up_sync(0xffffffffu, s, d);
            if (lane >= d) s += u;
        }
        if (lane < 16) woff[lane] = s - v;    // exclusive warp offset
        if (lane == 15) stot = s;             // row total T
    }
    __syncthreads();

    const float T = stot;
    // exp(r/tau) = ex2( (c*Cx) / (k+T) ),  Cx = 2/(tau*ln2)
    const float Cx = 2.0f / (0.95f * 0.69314718055994531f);
    float cfx = (woff[wid] + (incl - tsum)) * Cx;   // exclusive prefix * Cx
    float esum = 0.f;
    const float kbase = (float)(t * 8) + T;
    #pragma unroll
    for (int j = 0; j < 8; j++) {
        cfx = fmaf(labf[j], Cx, cfx);
        esum += ex2_approx(__fdividef(cfx, kbase + (float)(j + 1)));
    }

    // block reduce esum, lg2sum
    #pragma unroll
    for (int d = 16; d; d >>= 1) {
        esum   += __shfl_down_sync(0xffffffffu, esum, d);
        lg2sum += __shfl_down_sync(0xffffffffu, lg2sum, d);
    }
    __shared__ float se[16], sl[16];
    if (lane == 0) { se[wid] = esum; sl[wid] = lg2sum; }
    __syncthreads();

    if (t == 0) {
        float e = 0.f, l = 0.f;
        #pragma unroll
        for (int w = 0; w < 16; w++) { e += se[w]; l += sl[w]; }
        float lsum = l * 0.69314718055994531f;           // lg2 -> ln
        float2 pn = reinterpret_cast<const float2*>(rerank_y)[b];
        float hinge = fmaxf(0.f, pn.y - pn.x + 1.0f);
        float contrib = (hinge - lsum / e) * (1.0f / (float)B_ROWS);

        // L2 atomic accumulate (no fence, no L1 flush)
        float oldv = atomicAdd(&g_accum, contrib);
        unsigned z0 = opaque_zero(__float_as_uint(oldv));
        unsigned rank = atomicAdd(&g_count, 1u + z0);

        if (rank == B_ROWS - 1) {
            unsigned z1 = opaque_zero(rank);
            float total = atomicAdd(&g_accum, __uint_as_float(z1));  // += +0.0f
            out[0] = total;
            unsigned z2 = opaque_zero(__float_as_uint(total));
            atomicExch(&g_accum, __uint_as_float(z2));               // = 0.0f
            atomicExch(&g_count, z2);                                // = 0
        }
    }
}

extern "C" void kernel_launch(void* const* d_in, const int* in_sizes, int n_in,
                              void* d_out, int out_size)
{
    const float* rerank_y  = (const float*)d_in[0];   // (8192,1)
    const float* cut_y     = (const float*)d_in[1];   // (4096,4096,1)
    const int*   cut_label = (const int*)d_in[3];     // (4096,4096)
    float* out = (float*)d_out;

    mtcut_row_kernel<<<B_ROWS, BDIM>>>(cut_y, cut_label, rerank_y, out);
}